// round 2
// baseline (speedup 1.0000x reference)
#include <cuda_runtime.h>
#include <cstddef>

#define NB    2
#define NSEQ  2048
#define DIMSZ 2048
#define NH    16
#define HD    128
#define TTOT  (NB * NSEQ)        /* 4096 tokens */
#define INNER (NH * HD)          /* 2048 */
#define EPS   1e-5f
#define QK_SCALE 0.08838834764831845f   /* 1/sqrt(128) */

/* ------------------------------------------------------------------ */
/* Scratch (static device globals: no runtime allocation)              */
/* ------------------------------------------------------------------ */
__device__ float g_qkv[(size_t)TTOT * 3 * INNER];          /* [T, 3*H*HD] */
__device__ float g_q[(size_t)NB * NH * NSEQ * HD];         /* [B,H,N,HD]  */
__device__ float g_k[(size_t)NB * NH * NSEQ * HD];
__device__ float g_v[(size_t)NB * NH * NSEQ * HD];
__device__ float g_att[(size_t)TTOT * INNER];              /* [B,N,H*HD]  */

/* ------------------------------------------------------------------ */
/* SGEMM  C[M,N] = A[M,K] * B[N,K]^T   (both operands K-contiguous)    */
/* BM=BN=128, BK=8, 256 threads, 8x8 microtile.                        */
/* Double-buffered smem: LDG(next) overlaps FFMA(current); ONE         */
/* __syncthreads per mainloop iteration.                               */
/* ------------------------------------------------------------------ */
__global__ __launch_bounds__(256) void sgemm_nt(
    int M, int Nn, int K,
    const float* __restrict__ A,
    const float* __restrict__ B,
    float* __restrict__ C)
{
    __shared__ float As[2][8][132];   /* pad 132: conflict-free transposed STS */
    __shared__ float Bs[2][8][132];

    const int tid = threadIdx.x;
    const int tx  = tid & 15;
    const int ty  = tid >> 4;
    const int bm  = blockIdx.y * 128;
    const int bn  = blockIdx.x * 128;

    const int ar = tid >> 1;          /* row in tile 0..127 */
    const int ak = (tid & 1) * 4;     /* k offset 0 or 4    */

    const float* Ap = A + (size_t)(bm + ar) * K + ak;
    const float* Bp = B + (size_t)(bn + ar) * K + ak;

    float acc[8][8];
#pragma unroll
    for (int i = 0; i < 8; i++)
#pragma unroll
        for (int j = 0; j < 8; j++) acc[i][j] = 0.f;

    /* prologue: tile 0 -> buffer 0 */
    {
        float4 a4 = *(const float4*)(Ap);
        float4 b4 = *(const float4*)(Bp);
        As[0][ak + 0][ar] = a4.x; As[0][ak + 1][ar] = a4.y;
        As[0][ak + 2][ar] = a4.z; As[0][ak + 3][ar] = a4.w;
        Bs[0][ak + 0][ar] = b4.x; Bs[0][ak + 1][ar] = b4.y;
        Bs[0][ak + 2][ar] = b4.z; Bs[0][ak + 3][ar] = b4.w;
    }
    __syncthreads();

    int cur = 0;
    for (int k0 = 0; k0 < K; k0 += 8) {
        const bool has_next = (k0 + 8) < K;
        float4 a4, b4;
        if (has_next) {                       /* LDG overlapped with compute */
            a4 = *(const float4*)(Ap + k0 + 8);
            b4 = *(const float4*)(Bp + k0 + 8);
        }

#pragma unroll
        for (int k = 0; k < 8; k++) {
            float4 af0 = *(const float4*)&As[cur][k][ty * 8];
            float4 af1 = *(const float4*)&As[cur][k][ty * 8 + 4];
            float4 bf0 = *(const float4*)&Bs[cur][k][tx * 8];
            float4 bf1 = *(const float4*)&Bs[cur][k][tx * 8 + 4];
            float af[8], bf[8];
            af[0]=af0.x; af[1]=af0.y; af[2]=af0.z; af[3]=af0.w;
            af[4]=af1.x; af[5]=af1.y; af[6]=af1.z; af[7]=af1.w;
            bf[0]=bf0.x; bf[1]=bf0.y; bf[2]=bf0.z; bf[3]=bf0.w;
            bf[4]=bf1.x; bf[5]=bf1.y; bf[6]=bf1.z; bf[7]=bf1.w;
#pragma unroll
            for (int i = 0; i < 8; i++)
#pragma unroll
                for (int j = 0; j < 8; j++)
                    acc[i][j] += af[i] * bf[j];
        }

        if (has_next) {
            const int nxt = cur ^ 1;          /* write other buffer: no race  */
            As[nxt][ak + 0][ar] = a4.x; As[nxt][ak + 1][ar] = a4.y;
            As[nxt][ak + 2][ar] = a4.z; As[nxt][ak + 3][ar] = a4.w;
            Bs[nxt][ak + 0][ar] = b4.x; Bs[nxt][ak + 1][ar] = b4.y;
            Bs[nxt][ak + 2][ar] = b4.z; Bs[nxt][ak + 3][ar] = b4.w;
            __syncthreads();                  /* one barrier per iteration    */
            cur = nxt;
        }
    }

#pragma unroll
    for (int i = 0; i < 8; i++) {
        float* cp = C + (size_t)(bm + ty * 8 + i) * Nn + bn + tx * 8;
        float4 c0 = make_float4(acc[i][0], acc[i][1], acc[i][2], acc[i][3]);
        float4 c1 = make_float4(acc[i][4], acc[i][5], acc[i][6], acc[i][7]);
        *(float4*)cp       = c0;
        *(float4*)(cp + 4) = c1;
    }
}

/* ------------------------------------------------------------------ */
/* Fused RMSNorm + RoPE + transpose to [B,H,N,HD]                      */
/* grid (T, H), 128 threads: one (token, head); v is pass-through.     */
/* ------------------------------------------------------------------ */
__global__ __launch_bounds__(128) void norm_rope_kernel(
    const float* __restrict__ qkv,
    const float* __restrict__ q_gamma,
    const float* __restrict__ k_gamma,
    const float* __restrict__ freqs,
    float* __restrict__ Qo, float* __restrict__ Ko, float* __restrict__ Vo)
{
    const int t = blockIdx.x;          /* 0..4095 */
    const int h = blockIdx.y;          /* 0..15   */
    const int d = threadIdx.x;         /* 0..127  */
    const int b = t >> 11;
    const int n = t & (NSEQ - 1);

    const float* base = qkv + (size_t)t * (3 * INNER) + h * HD;
    float qv = base[d];
    float kv = base[INNER + d];
    float vv = base[2 * INNER + d];

    /* sum of squares over 128 lanes (4 warps) */
    __shared__ float red[8];
    float sq = qv * qv, sk = kv * kv;
#pragma unroll
    for (int off = 16; off >= 1; off >>= 1) {
        sq += __shfl_xor_sync(0xffffffffu, sq, off);
        sk += __shfl_xor_sync(0xffffffffu, sk, off);
    }
    const int warp = d >> 5, lane = d & 31;
    if (lane == 0) { red[warp] = sq; red[4 + warp] = sk; }
    __syncthreads();
    float sumq = red[0] + red[1] + red[2] + red[3];
    float sumk = red[4] + red[5] + red[6] + red[7];

    float rq = rsqrtf(sumq * (1.0f / HD) + EPS);
    float rk = rsqrtf(sumk * (1.0f / HD) + EPS);
    float qn = qv * rq * q_gamma[d];
    float kn = kv * rk * k_gamma[d];

    /* RoPE on adjacent pairs (2i, 2i+1) */
    const int p = d >> 1;
    const float* f = freqs + ((size_t)t * (HD / 2) + p) * 2;
    float c = f[0], s = f[1];
    float qp = __shfl_xor_sync(0xffffffffu, qn, 1);
    float kp = __shfl_xor_sync(0xffffffffu, kn, 1);
    float qo, ko;
    if ((d & 1) == 0) { qo = qn * c - qp * s;  ko = kn * c - kp * s; }
    else              { qo = qp * s + qn * c;  ko = kp * s + kn * c; }

    size_t oidx = (((size_t)(b * NH + h)) * NSEQ + n) * HD + d;
    Qo[oidx] = qo; Ko[oidx] = ko; Vo[oidx] = vv;
}

/* ------------------------------------------------------------------ */
/* Flash attention, fp32.  Block: 256 threads, 64-row Q tile, 64 KV.   */
/* smem: Qs[64][132] | (KTs[128][68]  alias  Vs[64][132]) | Ps[64][68] */
/* K is stored TRANSPOSED in smem so the S-gemm B-fragment reads are   */
/* contiguous float4s.                                                 */
/* ------------------------------------------------------------------ */
#define ATT_SMEM_FLOATS (64*132 + 128*68 + 64*68)   /* 21504 */
#define ATT_SMEM_BYTES  (ATT_SMEM_FLOATS * 4)       /* 86016 */

__global__ __launch_bounds__(256) void attn_kernel(
    const float* __restrict__ Q,
    const float* __restrict__ Kt,
    const float* __restrict__ V,
    float* __restrict__ O)
{
    extern __shared__ float sm[];
    float (*Qs)[132] = (float(*)[132])sm;                         /* 64x132  */
    float (*KTs)[68] = (float(*)[68])(sm + 64 * 132);             /* 128x68  */
    float (*Vs)[132] = (float(*)[132])(sm + 64 * 132);            /* alias   */
    float (*Ps)[68]  = (float(*)[68])(sm + 64 * 132 + 128 * 68);  /* 64x68   */

    const int tid = threadIdx.x;
    const int tx = tid & 15, ty = tid >> 4;
    const int bh = blockIdx.y;               /* b*H + h */
    const int q0 = blockIdx.x * 64;
    const int b  = bh >> 4, h = bh & 15;

    const float* Qb = Q  + (size_t)bh * NSEQ * HD;
    const float* Kb = Kt + (size_t)bh * NSEQ * HD;
    const float* Vb = V  + (size_t)bh * NSEQ * HD;

    /* load Q tile, pre-scaled by 1/sqrt(HD) */
    for (int i = tid; i < 64 * 32; i += 256) {
        int r = i >> 5, c4 = i & 31;
        float4 v4 = *(const float4*)&Qb[(size_t)(q0 + r) * HD + c4 * 4];
        v4.x *= QK_SCALE; v4.y *= QK_SCALE; v4.z *= QK_SCALE; v4.w *= QK_SCALE;
        *(float4*)&Qs[r][c4 * 4] = v4;
    }

    float m_i[4], l_i[4], o[4][8];
#pragma unroll
    for (int i = 0; i < 4; i++) {
        m_i[i] = -1e30f; l_i[i] = 0.f;
#pragma unroll
        for (int j = 0; j < 8; j++) o[i][j] = 0.f;
    }

    const int r0 = ty * 4, c0 = tx * 4, d0 = tx * 8;

    for (int kt = 0; kt < NSEQ; kt += 64) {
        __syncthreads();   /* prev-iter Vs/Ps readers done; Qs visible (iter 0) */

        /* K tile -> transposed smem. r varies within warp: conflict-free STS. */
        for (int i = tid; i < 64 * 32; i += 256) {
            int r = i & 63, c4 = i >> 6;
            float4 v4 = *(const float4*)&Kb[(size_t)(kt + r) * HD + c4 * 4];
            KTs[c4 * 4 + 0][r] = v4.x;
            KTs[c4 * 4 + 1][r] = v4.y;
            KTs[c4 * 4 + 2][r] = v4.z;
            KTs[c4 * 4 + 3][r] = v4.w;
        }
        __syncthreads();

        /* S = (Q*scale) K^T : 64x64x128, 4x4 per thread */
        float s[4][4];
#pragma unroll
        for (int i = 0; i < 4; i++)
#pragma unroll
            for (int j = 0; j < 4; j++) s[i][j] = 0.f;

#pragma unroll 8
        for (int d4 = 0; d4 < 32; d4++) {
            float aq[4][4];
#pragma unroll
            for (int i = 0; i < 4; i++) {
                float4 a4 = *(const float4*)&Qs[r0 + i][d4 * 4];
                aq[i][0] = a4.x; aq[i][1] = a4.y; aq[i][2] = a4.z; aq[i][3] = a4.w;
            }
#pragma unroll
            for (int dd = 0; dd < 4; dd++) {
                float4 b4 = *(const float4*)&KTs[d4 * 4 + dd][c0];
#pragma unroll
                for (int i = 0; i < 4; i++) {
                    s[i][0] += aq[i][dd] * b4.x;
                    s[i][1] += aq[i][dd] * b4.y;
                    s[i][2] += aq[i][dd] * b4.z;
                    s[i][3] += aq[i][dd] * b4.w;
                }
            }
        }

        /* online softmax: row reduce across the 16 tx lanes (shfl width 16) */
        float p[4][4];
#pragma unroll
        for (int i = 0; i < 4; i++) {
            float tm = fmaxf(fmaxf(s[i][0], s[i][1]), fmaxf(s[i][2], s[i][3]));
#pragma unroll
            for (int off = 8; off >= 1; off >>= 1)
                tm = fmaxf(tm, __shfl_xor_sync(0xffffffffu, tm, off));
            float mn   = fmaxf(m_i[i], tm);
            float corr = __expf(m_i[i] - mn);
            m_i[i] = mn;
            float ls = 0.f;
#pragma unroll
            for (int j = 0; j < 4; j++) { p[i][j] = __expf(s[i][j] - mn); ls += p[i][j]; }
#pragma unroll
            for (int off = 8; off >= 1; off >>= 1)
                ls += __shfl_xor_sync(0xffffffffu, ls, off);
            l_i[i] = l_i[i] * corr + ls;
#pragma unroll
            for (int j = 0; j < 8; j++) o[i][j] *= corr;
        }
        __syncthreads();   /* done reading K from aliased buffer */

        /* store P; load V over the K buffer */
#pragma unroll
        for (int i = 0; i < 4; i++)
#pragma unroll
            for (int j = 0; j < 4; j++)
                Ps[r0 + i][c0 + j] = p[i][j];

        for (int i = tid; i < 64 * 32; i += 256) {
            int r = i >> 5, c4 = i & 31;
            *(float4*)&Vs[r][c4 * 4] =
                *(const float4*)&Vb[(size_t)(kt + r) * HD + c4 * 4];
        }
        __syncthreads();

        /* O += P V : 64x128x64, 4 rows x 8 cols per thread */
#pragma unroll 8
        for (int k = 0; k < 64; k++) {
            float pr[4];
#pragma unroll
            for (int i = 0; i < 4; i++) pr[i] = Ps[r0 + i][k];
            float4 v0 = *(const float4*)&Vs[k][d0];
            float4 v1 = *(const float4*)&Vs[k][d0 + 4];
#pragma unroll
            for (int i = 0; i < 4; i++) {
                o[i][0] += pr[i] * v0.x; o[i][1] += pr[i] * v0.y;
                o[i][2] += pr[i] * v0.z; o[i][3] += pr[i] * v0.w;
                o[i][4] += pr[i] * v1.x; o[i][5] += pr[i] * v1.y;
                o[i][6] += pr[i] * v1.z; o[i][7] += pr[i] * v1.w;
            }
        }
    }

    /* epilogue: normalize, write [B,N,H*HD] */
#pragma unroll
    for (int i = 0; i < 4; i++) {
        float inv = 1.0f / l_i[i];
        int n = q0 + r0 + i;
        float* dst = O + ((size_t)b * NSEQ + n) * INNER + h * HD + d0;
        float4 w0 = make_float4(o[i][0]*inv, o[i][1]*inv, o[i][2]*inv, o[i][3]*inv);
        float4 w1 = make_float4(o[i][4]*inv, o[i][5]*inv, o[i][6]*inv, o[i][7]*inv);
        *(float4*)dst       = w0;
        *(float4*)(dst + 4) = w1;
    }
}

/* ------------------------------------------------------------------ */
extern "C" void kernel_launch(void* const* d_in, const int* in_sizes, int n_in,
                              void* d_out, int out_size)
{
    /* identify inputs by element count (robust to ordering) */
    const float *x = nullptr, *Wqkv = nullptr, *qg = nullptr, *kg = nullptr,
                *Wout = nullptr, *freqs = nullptr;
    for (int i = 0; i < n_in; i++) {
        const float* p = (const float*)d_in[i];
        switch (in_sizes[i]) {
            case 8388608:  x     = p; break;   /* [2,2048,2048]      */
            case 12582912: Wqkv  = p; break;   /* [6144,2048]        */
            case 4194304:  Wout  = p; break;   /* [2048,2048]        */
            case 524288:   freqs = p; break;   /* [2,2048,64,2]      */
            case 128:      if (!qg) qg = p; else kg = p; break;
            default: break;
        }
    }

    float *qkv, *q, *k, *v, *att;
    cudaGetSymbolAddress((void**)&qkv, g_qkv);
    cudaGetSymbolAddress((void**)&q,   g_q);
    cudaGetSymbolAddress((void**)&k,   g_k);
    cudaGetSymbolAddress((void**)&v,   g_v);
    cudaGetSymbolAddress((void**)&att, g_att);

    cudaFuncSetAttribute(attn_kernel,
                         cudaFuncAttributeMaxDynamicSharedMemorySize,
                         ATT_SMEM_BYTES);

    /* 1. QKV projection: [4096,6144] = x[4096,2048] @ Wqkv[6144,2048]^T */
    sgemm_nt<<<dim3(3 * INNER / 128, TTOT / 128), 256>>>(
        TTOT, 3 * INNER, DIMSZ, x, Wqkv, qkv);

    /* 2. RMSNorm + RoPE + transpose to [B,H,N,HD] */
    norm_rope_kernel<<<dim3(TTOT, NH), 128>>>(qkv, qg, kg, freqs, q, k, v);

    /* 3. Attention -> [B,N,H*HD] */
    attn_kernel<<<dim3(NSEQ / 64, NB * NH), 256, ATT_SMEM_BYTES>>>(q, k, v, att);

    /* 4. Output projection: [4096,2048] = att @ Wout[2048,2048]^T */
    sgemm_nt<<<dim3(DIMSZ / 128, TTOT / 128), 256>>>(
        TTOT, DIMSZ, INNER, att, Wout, (float*)d_out);
}

// round 10
// speedup vs baseline: 1.4753x; 1.4753x over previous
#include <cuda_runtime.h>
#include <cuda_bf16.h>
#include <cstdint>
#include <cstddef>

#define NB    2
#define NSEQ  2048
#define DIMSZ 2048
#define NH    16
#define HD    128
#define TTOT  (NB * NSEQ)        /* 4096 tokens */
#define INNER (NH * HD)          /* 2048 */
#define EPS   1e-5f
#define QK_SCALE 0.08838834764831845f   /* 1/sqrt(128) */
#define GK3   (3 * DIMSZ)        /* 6144: split-K' for both GEMMs (K=2048) */

/* ------------------------------------------------------------------ */
/* Scratch (static device globals: no runtime allocation)              */
/* ------------------------------------------------------------------ */
__device__ float g_qkv[(size_t)TTOT * 3 * INNER];          /* [T, 3*H*HD] */
__device__ float g_q[(size_t)NB * NH * NSEQ * HD];         /* [B,H,N,HD]  */
__device__ float g_k[(size_t)NB * NH * NSEQ * HD];
__device__ float g_v[(size_t)NB * NH * NSEQ * HD];
__device__ float g_att[(size_t)TTOT * INNER];              /* [B,N,H*HD]  */
__device__ __align__(256) __nv_bfloat16 g_A3[(size_t)TTOT * GK3];
__device__ __align__(256) __nv_bfloat16 g_B3[(size_t)(3 * INNER) * GK3];

/* ------------------------------------------------------------------ */
/* mma.sync helpers (family-portable PTX: works on target sm_103)      */
/* ------------------------------------------------------------------ */
__device__ __forceinline__ uint32_t smem_u32(const void* p) {
    uint32_t a;
    asm("{ .reg .u64 t; cvta.to.shared.u64 t, %1; cvt.u32.u64 %0, t; }"
        : "=r"(a) : "l"(p));
    return a;
}
__device__ __forceinline__ void ldsm_x4(uint32_t* r, uint32_t addr) {
    asm volatile("ldmatrix.sync.aligned.m8n8.x4.shared.b16 {%0,%1,%2,%3}, [%4];"
                 : "=r"(r[0]), "=r"(r[1]), "=r"(r[2]), "=r"(r[3]) : "r"(addr));
}
__device__ __forceinline__ void ldsm_x2(uint32_t* r, uint32_t addr) {
    asm volatile("ldmatrix.sync.aligned.m8n8.x2.shared.b16 {%0,%1}, [%2];"
                 : "=r"(r[0]), "=r"(r[1]) : "r"(addr));
}
__device__ __forceinline__ void mma_bf16(float* c, const uint32_t* a,
                                         const uint32_t* b) {
    asm volatile(
        "mma.sync.aligned.m16n8k16.row.col.f32.bf16.bf16.f32 "
        "{%0,%1,%2,%3}, {%4,%5,%6,%7}, {%8,%9}, {%0,%1,%2,%3};"
        : "+f"(c[0]), "+f"(c[1]), "+f"(c[2]), "+f"(c[3])
        : "r"(a[0]), "r"(a[1]), "r"(a[2]), "r"(a[3]), "r"(b[0]), "r"(b[1]));
}

/* ------------------------------------------------------------------ */
/* Split-3 conversion: src fp32 [R,K] -> dst bf16 [R,3K]               */
/* lo_slot=2 (A pattern: hi,hi,lo)  lo_slot=1 (B pattern: hi,lo,hi)    */
/* ------------------------------------------------------------------ */
__global__ __launch_bounds__(256) void split3_kernel(
    const float* __restrict__ src, __nv_bfloat16* __restrict__ dst,
    int R, int K, int lo_slot)
{
    size_t i = (size_t)blockIdx.x * 256 + threadIdx.x;   /* quad index */
    size_t total = ((size_t)R * K) >> 2;
    if (i >= total) return;
    float4 v = ((const float4*)src)[i];
    int kq = K >> 2;
    int r  = (int)(i / kq);
    int k4 = (int)(i % kq) * 4;
    float vv[4] = {v.x, v.y, v.z, v.w};
    __nv_bfloat16 h[4], l[4];
#pragma unroll
    for (int j = 0; j < 4; j++) {
        h[j] = __float2bfloat16(vv[j]);
        l[j] = __float2bfloat16(vv[j] - __bfloat162float(h[j]));
    }
    __nv_bfloat162 h01, h23, l01, l23;
    h01.x = h[0]; h01.y = h[1]; h23.x = h[2]; h23.y = h[3];
    l01.x = l[0]; l01.y = l[1]; l23.x = l[2]; l23.y = l[3];
    __nv_bfloat16* row = dst + (size_t)r * 3 * K;
    int hi2 = 3 - lo_slot;
    *(__nv_bfloat162*)(row + k4)               = h01;
    *(__nv_bfloat162*)(row + k4 + 2)           = h23;
    *(__nv_bfloat162*)(row + hi2 * K + k4)     = h01;
    *(__nv_bfloat162*)(row + hi2 * K + k4 + 2) = h23;
    *(__nv_bfloat162*)(row + lo_slot * K + k4)     = l01;
    *(__nv_bfloat162*)(row + lo_slot * K + k4 + 2) = l23;
}

/* ------------------------------------------------------------------ */
/* HMMA GEMM  C[M,N] = A3[M,K3] * B3[N,K3]^T   (both K-contiguous)     */
/* BM=BN=128, BK=32, 256 thr = 8 warps (2m x 4n), warp tile 64x32,     */
/* m16n8k16 bf16 mma, fp32 acc, double-buffered smem (1 sync/iter).    */
/* smem rows padded to 40 bf16 (80B): ldmatrix phases conflict-free.   */
/* ------------------------------------------------------------------ */
#define G_STRIDE 40   /* bf16 elements per smem row (32 used) */

__global__ __launch_bounds__(256, 2) void gemm_mma(
    int M, int Nn,
    const __nv_bfloat16* __restrict__ A,
    const __nv_bfloat16* __restrict__ B,
    float* __restrict__ C)
{
    __shared__ __align__(16) __nv_bfloat16 sA[2][128][G_STRIDE];
    __shared__ __align__(16) __nv_bfloat16 sB[2][128][G_STRIDE];

    const int tid  = threadIdx.x;
    const int lane = tid & 31;
    const int wid  = tid >> 5;
    const int wm   = wid & 1;          /* 2 warps along M */
    const int wn   = wid >> 1;         /* 4 warps along N */
    const int bm   = blockIdx.y * 128;
    const int bn   = blockIdx.x * 128;

    /* global-load assignment: ids tid, tid+256; r = id/4, seg = id%4 */
    const int r0g = tid >> 2, s0g = (tid & 3);          /* id = tid      */
    const int r1g = (tid + 256) >> 2, s1g = s0g;        /* id = tid+256  */

    const __nv_bfloat16* Ag0 = A + (size_t)(bm + r0g) * GK3 + s0g * 8;
    const __nv_bfloat16* Ag1 = A + (size_t)(bm + r1g) * GK3 + s1g * 8;
    const __nv_bfloat16* Bg0 = B + (size_t)(bn + r0g) * GK3 + s0g * 8;
    const __nv_bfloat16* Bg1 = B + (size_t)(bn + r1g) * GK3 + s1g * 8;

    float acc[4][4][4];
#pragma unroll
    for (int i = 0; i < 4; i++)
#pragma unroll
        for (int j = 0; j < 4; j++)
#pragma unroll
            for (int e = 0; e < 4; e++) acc[i][j][e] = 0.f;

    /* smem byte addresses for ldmatrix */
    const uint32_t sAb = smem_u32(&sA[0][0][0]);
    const uint32_t sBb = smem_u32(&sB[0][0][0]);
    const uint32_t BUFB = 128 * G_STRIDE * 2;           /* bytes per buffer */

    /* A frag addr: row = wm*64 + mi*16 + (lane&15), colhalf = lane>>4   */
    const int aRow = wm * 64 + (lane & 15);
    const int aCol = (lane >> 4) * 8;
    /* B frag addr: row = wn*32 + ni*8 + (l&7), half = (l>>3), l=lane&15 */
    const int bRow = wn * 32 + (lane & 7);
    const int bCol = ((lane >> 3) & 1) * 8;

    /* prologue: tile 0 -> buffer 0 */
    {
        uint4 a0 = *(const uint4*)Ag0;
        uint4 a1 = *(const uint4*)Ag1;
        uint4 b0 = *(const uint4*)Bg0;
        uint4 b1 = *(const uint4*)Bg1;
        *(uint4*)&sA[0][r0g][s0g * 8] = a0;
        *(uint4*)&sA[0][r1g][s1g * 8] = a1;
        *(uint4*)&sB[0][r0g][s0g * 8] = b0;
        *(uint4*)&sB[0][r1g][s1g * 8] = b1;
    }
    __syncthreads();

    const int NIT = GK3 / 32;   /* 192 */
    int cur = 0;

    for (int c = 0; c < NIT; c++) {
        const bool has_next = (c + 1) < NIT;
        uint4 la0, la1, lb0, lb1;
        if (has_next) {
            const size_t off = (size_t)(c + 1) * 32;
            la0 = *(const uint4*)(Ag0 + off);
            la1 = *(const uint4*)(Ag1 + off);
            lb0 = *(const uint4*)(Bg0 + off);
            lb1 = *(const uint4*)(Bg1 + off);
        }

        const uint32_t aBase = sAb + cur * BUFB;
        const uint32_t bBase = sBb + cur * BUFB;
#pragma unroll
        for (int ks = 0; ks < 2; ks++) {
            uint32_t af[4][4], bf[4][2];
#pragma unroll
            for (int mi = 0; mi < 4; mi++)
                ldsm_x4(af[mi], aBase +
                        (uint32_t)((aRow + mi * 16) * (G_STRIDE * 2)
                                   + (ks * 16 + aCol) * 2));
#pragma unroll
            for (int ni = 0; ni < 4; ni++)
                ldsm_x2(bf[ni], bBase +
                        (uint32_t)((bRow + ni * 8) * (G_STRIDE * 2)
                                   + (ks * 16 + bCol) * 2));
#pragma unroll
            for (int mi = 0; mi < 4; mi++)
#pragma unroll
                for (int ni = 0; ni < 4; ni++)
                    mma_bf16(acc[mi][ni], af[mi], bf[ni]);
        }

        if (has_next) {
            const int nxt = cur ^ 1;
            *(uint4*)&sA[nxt][r0g][s0g * 8] = la0;
            *(uint4*)&sA[nxt][r1g][s1g * 8] = la1;
            *(uint4*)&sB[nxt][r0g][s0g * 8] = lb0;
            *(uint4*)&sB[nxt][r1g][s1g * 8] = lb1;
            __syncthreads();
            cur = nxt;
        }
    }

    /* epilogue: fragment layout -> direct float2 STG */
    const int erow = bm + wm * 64 + (lane >> 2);
    const int ecol = bn + wn * 32 + (lane & 3) * 2;
#pragma unroll
    for (int mi = 0; mi < 4; mi++)
#pragma unroll
        for (int ni = 0; ni < 4; ni++) {
            float* p0 = C + (size_t)(erow + mi * 16) * Nn + ecol + ni * 8;
            float* p1 = p0 + 8 * Nn;
            *(float2*)p0 = make_float2(acc[mi][ni][0], acc[mi][ni][1]);
            *(float2*)p1 = make_float2(acc[mi][ni][2], acc[mi][ni][3]);
        }
}

/* ------------------------------------------------------------------ */
/* Fused RMSNorm + RoPE + transpose to [B,H,N,HD]                      */
/* ------------------------------------------------------------------ */
__global__ __launch_bounds__(128) void norm_rope_kernel(
    const float* __restrict__ qkv,
    const float* __restrict__ q_gamma,
    const float* __restrict__ k_gamma,
    const float* __restrict__ freqs,
    float* __restrict__ Qo, float* __restrict__ Ko, float* __restrict__ Vo)
{
    const int t = blockIdx.x;
    const int h = blockIdx.y;
    const int d = threadIdx.x;
    const int b = t >> 11;
    const int n = t & (NSEQ - 1);

    const float* base = qkv + (size_t)t * (3 * INNER) + h * HD;
    float qv = base[d];
    float kv = base[INNER + d];
    float vv = base[2 * INNER + d];

    __shared__ float red[8];
    float sq = qv * qv, sk = kv * kv;
#pragma unroll
    for (int off = 16; off >= 1; off >>= 1) {
        sq += __shfl_xor_sync(0xffffffffu, sq, off);
        sk += __shfl_xor_sync(0xffffffffu, sk, off);
    }
    const int warp = d >> 5, lane = d & 31;
    if (lane == 0) { red[warp] = sq; red[4 + warp] = sk; }
    __syncthreads();
    float sumq = red[0] + red[1] + red[2] + red[3];
    float sumk = red[4] + red[5] + red[6] + red[7];

    float rq = rsqrtf(sumq * (1.0f / HD) + EPS);
    float rk = rsqrtf(sumk * (1.0f / HD) + EPS);
    float qn = qv * rq * q_gamma[d];
    float kn = kv * rk * k_gamma[d];

    const int p = d >> 1;
    const float* f = freqs + ((size_t)t * (HD / 2) + p) * 2;
    float c = f[0], s = f[1];
    float qp = __shfl_xor_sync(0xffffffffu, qn, 1);
    float kp = __shfl_xor_sync(0xffffffffu, kn, 1);
    float qo, ko;
    if ((d & 1) == 0) { qo = qn * c - qp * s;  ko = kn * c - kp * s; }
    else              { qo = qp * s + qn * c;  ko = kp * s + kn * c; }

    size_t oidx = (((size_t)(b * NH + h)) * NSEQ + n) * HD + d;
    Qo[oidx] = qo; Ko[oidx] = ko; Vo[oidx] = vv;
}

/* ------------------------------------------------------------------ */
/* Flash attention, fp32 (unchanged from passing round-2 kernel).      */
/* ------------------------------------------------------------------ */
#define ATT_SMEM_FLOATS (64*132 + 128*68 + 64*68)
#define ATT_SMEM_BYTES  (ATT_SMEM_FLOATS * 4)

__global__ __launch_bounds__(256) void attn_kernel(
    const float* __restrict__ Q,
    const float* __restrict__ Kt,
    const float* __restrict__ V,
    float* __restrict__ O)
{
    extern __shared__ float sm[];
    float (*Qs)[132] = (float(*)[132])sm;
    float (*KTs)[68] = (float(*)[68])(sm + 64 * 132);
    float (*Vs)[132] = (float(*)[132])(sm + 64 * 132);
    float (*Ps)[68]  = (float(*)[68])(sm + 64 * 132 + 128 * 68);

    const int tid = threadIdx.x;
    const int tx = tid & 15, ty = tid >> 4;
    const int bh = blockIdx.y;
    const int q0 = blockIdx.x * 64;
    const int b  = bh >> 4, h = bh & 15;

    const float* Qb = Q  + (size_t)bh * NSEQ * HD;
    const float* Kb = Kt + (size_t)bh * NSEQ * HD;
    const float* Vb = V  + (size_t)bh * NSEQ * HD;

    for (int i = tid; i < 64 * 32; i += 256) {
        int r = i >> 5, c4 = i & 31;
        float4 v4 = *(const float4*)&Qb[(size_t)(q0 + r) * HD + c4 * 4];
        v4.x *= QK_SCALE; v4.y *= QK_SCALE; v4.z *= QK_SCALE; v4.w *= QK_SCALE;
        *(float4*)&Qs[r][c4 * 4] = v4;
    }

    float m_i[4], l_i[4], o[4][8];
#pragma unroll
    for (int i = 0; i < 4; i++) {
        m_i[i] = -1e30f; l_i[i] = 0.f;
#pragma unroll
        for (int j = 0; j < 8; j++) o[i][j] = 0.f;
    }

    const int r0 = ty * 4, c0 = tx * 4, d0 = tx * 8;

    for (int kt = 0; kt < NSEQ; kt += 64) {
        __syncthreads();

        for (int i = tid; i < 64 * 32; i += 256) {
            int r = i & 63, c4 = i >> 6;
            float4 v4 = *(const float4*)&Kb[(size_t)(kt + r) * HD + c4 * 4];
            KTs[c4 * 4 + 0][r] = v4.x;
            KTs[c4 * 4 + 1][r] = v4.y;
            KTs[c4 * 4 + 2][r] = v4.z;
            KTs[c4 * 4 + 3][r] = v4.w;
        }
        __syncthreads();

        float s[4][4];
#pragma unroll
        for (int i = 0; i < 4; i++)
#pragma unroll
            for (int j = 0; j < 4; j++) s[i][j] = 0.f;

#pragma unroll 8
        for (int d4 = 0; d4 < 32; d4++) {
            float aq[4][4];
#pragma unroll
            for (int i = 0; i < 4; i++) {
                float4 a4 = *(const float4*)&Qs[r0 + i][d4 * 4];
                aq[i][0] = a4.x; aq[i][1] = a4.y; aq[i][2] = a4.z; aq[i][3] = a4.w;
            }
#pragma unroll
            for (int dd = 0; dd < 4; dd++) {
                float4 b4 = *(const float4*)&KTs[d4 * 4 + dd][c0];
#pragma unroll
                for (int i = 0; i < 4; i++) {
                    s[i][0] += aq[i][dd] * b4.x;
                    s[i][1] += aq[i][dd] * b4.y;
                    s[i][2] += aq[i][dd] * b4.z;
                    s[i][3] += aq[i][dd] * b4.w;
                }
            }
        }

        float p[4][4];
#pragma unroll
        for (int i = 0; i < 4; i++) {
            float tm = fmaxf(fmaxf(s[i][0], s[i][1]), fmaxf(s[i][2], s[i][3]));
#pragma unroll
            for (int off = 8; off >= 1; off >>= 1)
                tm = fmaxf(tm, __shfl_xor_sync(0xffffffffu, tm, off));
            float mn   = fmaxf(m_i[i], tm);
            float corr = __expf(m_i[i] - mn);
            m_i[i] = mn;
            float ls = 0.f;
#pragma unroll
            for (int j = 0; j < 4; j++) { p[i][j] = __expf(s[i][j] - mn); ls += p[i][j]; }
#pragma unroll
            for (int off = 8; off >= 1; off >>= 1)
                ls += __shfl_xor_sync(0xffffffffu, ls, off);
            l_i[i] = l_i[i] * corr + ls;
#pragma unroll
            for (int j = 0; j < 8; j++) o[i][j] *= corr;
        }
        __syncthreads();

#pragma unroll
        for (int i = 0; i < 4; i++)
#pragma unroll
            for (int j = 0; j < 4; j++)
                Ps[r0 + i][c0 + j] = p[i][j];

        for (int i = tid; i < 64 * 32; i += 256) {
            int r = i >> 5, c4 = i & 31;
            *(float4*)&Vs[r][c4 * 4] =
                *(const float4*)&Vb[(size_t)(kt + r) * HD + c4 * 4];
        }
        __syncthreads();

#pragma unroll 8
        for (int k = 0; k < 64; k++) {
            float pr[4];
#pragma unroll
            for (int i = 0; i < 4; i++) pr[i] = Ps[r0 + i][k];
            float4 v0 = *(const float4*)&Vs[k][d0];
            float4 v1 = *(const float4*)&Vs[k][d0 + 4];
#pragma unroll
            for (int i = 0; i < 4; i++) {
                o[i][0] += pr[i] * v0.x; o[i][1] += pr[i] * v0.y;
                o[i][2] += pr[i] * v0.z; o[i][3] += pr[i] * v0.w;
                o[i][4] += pr[i] * v1.x; o[i][5] += pr[i] * v1.y;
                o[i][6] += pr[i] * v1.z; o[i][7] += pr[i] * v1.w;
            }
        }
    }

#pragma unroll
    for (int i = 0; i < 4; i++) {
        float inv = 1.0f / l_i[i];
        int n = q0 + r0 + i;
        float* dst = O + ((size_t)b * NSEQ + n) * INNER + h * HD + d0;
        float4 w0 = make_float4(o[i][0]*inv, o[i][1]*inv, o[i][2]*inv, o[i][3]*inv);
        float4 w1 = make_float4(o[i][4]*inv, o[i][5]*inv, o[i][6]*inv, o[i][7]*inv);
        *(float4*)dst       = w0;
        *(float4*)(dst + 4) = w1;
    }
}

/* ------------------------------------------------------------------ */
extern "C" void kernel_launch(void* const* d_in, const int* in_sizes, int n_in,
                              void* d_out, int out_size)
{
    const float *x = nullptr, *Wqkv = nullptr, *qg = nullptr, *kg = nullptr,
                *Wout = nullptr, *freqs = nullptr;
    for (int i = 0; i < n_in; i++) {
        const float* p = (const float*)d_in[i];
        switch (in_sizes[i]) {
            case 8388608:  x     = p; break;   /* [2,2048,2048] */
            case 12582912: Wqkv  = p; break;   /* [6144,2048]   */
            case 4194304:  Wout  = p; break;   /* [2048,2048]   */
            case 524288:   freqs = p; break;   /* [2,2048,64,2] */
            case 128:      if (!qg) qg = p; else kg = p; break;
            default: break;
        }
    }

    float *qkv, *q, *k, *v, *att;
    __nv_bfloat16 *A3, *B3;
    cudaGetSymbolAddress((void**)&qkv, g_qkv);
    cudaGetSymbolAddress((void**)&q,   g_q);
    cudaGetSymbolAddress((void**)&k,   g_k);
    cudaGetSymbolAddress((void**)&v,   g_v);
    cudaGetSymbolAddress((void**)&att, g_att);
    cudaGetSymbolAddress((void**)&A3,  g_A3);
    cudaGetSymbolAddress((void**)&B3,  g_B3);

    cudaFuncSetAttribute(attn_kernel,
                         cudaFuncAttributeMaxDynamicSharedMemorySize,
                         ATT_SMEM_BYTES);

    /* 1. QKV projection via bf16 mma (3-term split, fp32 accum) */
    {
        size_t qa = ((size_t)TTOT * DIMSZ) >> 2;
        size_t qb = ((size_t)(3 * INNER) * DIMSZ) >> 2;
        split3_kernel<<<(int)((qa + 255) / 256), 256>>>(x,    A3, TTOT,      DIMSZ, 2);
        split3_kernel<<<(int)((qb + 255) / 256), 256>>>(Wqkv, B3, 3 * INNER, DIMSZ, 1);
        gemm_mma<<<dim3(3 * INNER / 128, TTOT / 128), 256>>>(
            TTOT, 3 * INNER, A3, B3, qkv);
    }

    /* 2. RMSNorm + RoPE + transpose */
    norm_rope_kernel<<<dim3(TTOT, NH), 128>>>(qkv, qg, kg, freqs, q, k, v);

    /* 3. Attention -> [B,N,H*HD] */
    attn_kernel<<<dim3(NSEQ / 64, NB * NH), 256, ATT_SMEM_BYTES>>>(q, k, v, att);

    /* 4. Output projection via bf16 mma */
    {
        size_t qa = ((size_t)TTOT * INNER) >> 2;
        size_t qb = ((size_t)DIMSZ * INNER) >> 2;
        split3_kernel<<<(int)((qa + 255) / 256), 256>>>(att,  A3, TTOT,  INNER, 2);
        split3_kernel<<<(int)((qb + 255) / 256), 256>>>(Wout, B3, DIMSZ, INNER, 1);
        gemm_mma<<<dim3(DIMSZ / 128, TTOT / 128), 256>>>(
            TTOT, DIMSZ, A3, B3, (float*)d_out);
    }
}

// round 16
// speedup vs baseline: 2.1683x; 1.4697x over previous
#include <cuda_runtime.h>
#include <cuda_bf16.h>
#include <cstdint>
#include <cstddef>

#define NB    2
#define NSEQ  2048
#define DIMSZ 2048
#define NH    16
#define HD    128
#define TTOT  (NB * NSEQ)        /* 4096 tokens */
#define INNER (NH * HD)          /* 2048 */
#define EPS   1e-5f
#define QK_SCALE 0.08838834764831845f   /* 1/sqrt(128) */
#define GK3   (3 * DIMSZ)        /* 6144: split-K' for both GEMMs (K=2048) */

/* ------------------------------------------------------------------ */
/* Scratch (static device globals: no runtime allocation)              */
/* ------------------------------------------------------------------ */
__device__ float g_qkv[(size_t)TTOT * 3 * INNER];          /* [T, 3*H*HD] */
__device__ float g_q[(size_t)NB * NH * NSEQ * HD];         /* [B,H,N,HD]  */
__device__ float g_k[(size_t)NB * NH * NSEQ * HD];
__device__ float g_v[(size_t)NB * NH * NSEQ * HD];
__device__ float g_att[(size_t)TTOT * INNER];              /* [B,N,H*HD]  */
__device__ __align__(256) __nv_bfloat16 g_A3[(size_t)TTOT * GK3];
__device__ __align__(256) __nv_bfloat16 g_B3[(size_t)(3 * INNER) * GK3];

/* ------------------------------------------------------------------ */
/* mma.sync helpers (family-portable PTX: works on target sm_103)      */
/* ------------------------------------------------------------------ */
__device__ __forceinline__ uint32_t smem_u32(const void* p) {
    uint32_t a;
    asm("{ .reg .u64 t; cvta.to.shared.u64 t, %1; cvt.u32.u64 %0, t; }"
        : "=r"(a) : "l"(p));
    return a;
}
__device__ __forceinline__ void ldsm_x4(uint32_t* r, uint32_t addr) {
    asm volatile("ldmatrix.sync.aligned.m8n8.x4.shared.b16 {%0,%1,%2,%3}, [%4];"
                 : "=r"(r[0]), "=r"(r[1]), "=r"(r[2]), "=r"(r[3]) : "r"(addr));
}
__device__ __forceinline__ void ldsm_x2(uint32_t* r, uint32_t addr) {
    asm volatile("ldmatrix.sync.aligned.m8n8.x2.shared.b16 {%0,%1}, [%2];"
                 : "=r"(r[0]), "=r"(r[1]) : "r"(addr));
}
__device__ __forceinline__ void ldsm_x2_t(uint32_t* r, uint32_t addr) {
    asm volatile("ldmatrix.sync.aligned.m8n8.x2.trans.shared.b16 {%0,%1}, [%2];"
                 : "=r"(r[0]), "=r"(r[1]) : "r"(addr));
}
__device__ __forceinline__ void mma_bf16(float* c, const uint32_t* a,
                                         const uint32_t* b) {
    asm volatile(
        "mma.sync.aligned.m16n8k16.row.col.f32.bf16.bf16.f32 "
        "{%0,%1,%2,%3}, {%4,%5,%6,%7}, {%8,%9}, {%0,%1,%2,%3};"
        : "+f"(c[0]), "+f"(c[1]), "+f"(c[2]), "+f"(c[3])
        : "r"(a[0]), "r"(a[1]), "r"(a[2]), "r"(a[3]), "r"(b[0]), "r"(b[1]));
}
/* pack (even,odd) fp32 -> bf16x2 (lo=even, hi=odd) */
__device__ __forceinline__ uint32_t cvt2_bf16(float even, float odd) {
    uint32_t r;
    asm("cvt.rn.bf16x2.f32 %0, %1, %2;" : "=r"(r) : "f"(odd), "f"(even));
    return r;
}
/* split pair into bf16 hi + bf16 residual lo */
__device__ __forceinline__ void split2(float even, float odd,
                                       uint32_t& hi, uint32_t& lo) {
    hi = cvt2_bf16(even, odd);
    float he = __uint_as_float(hi << 16);
    float ho = __uint_as_float(hi & 0xFFFF0000u);
    lo = cvt2_bf16(even - he, odd - ho);
}

/* ------------------------------------------------------------------ */
/* Split-3 conversion: src fp32 [R,K] -> dst bf16 [R,3K]               */
/* ------------------------------------------------------------------ */
__global__ __launch_bounds__(256) void split3_kernel(
    const float* __restrict__ src, __nv_bfloat16* __restrict__ dst,
    int R, int K, int lo_slot)
{
    size_t i = (size_t)blockIdx.x * 256 + threadIdx.x;
    size_t total = ((size_t)R * K) >> 2;
    if (i >= total) return;
    float4 v = ((const float4*)src)[i];
    int kq = K >> 2;
    int r  = (int)(i / kq);
    int k4 = (int)(i % kq) * 4;
    float vv[4] = {v.x, v.y, v.z, v.w};
    __nv_bfloat16 h[4], l[4];
#pragma unroll
    for (int j = 0; j < 4; j++) {
        h[j] = __float2bfloat16(vv[j]);
        l[j] = __float2bfloat16(vv[j] - __bfloat162float(h[j]));
    }
    __nv_bfloat162 h01, h23, l01, l23;
    h01.x = h[0]; h01.y = h[1]; h23.x = h[2]; h23.y = h[3];
    l01.x = l[0]; l01.y = l[1]; l23.x = l[2]; l23.y = l[3];
    __nv_bfloat16* row = dst + (size_t)r * 3 * K;
    int hi2 = 3 - lo_slot;
    *(__nv_bfloat162*)(row + k4)               = h01;
    *(__nv_bfloat162*)(row + k4 + 2)           = h23;
    *(__nv_bfloat162*)(row + hi2 * K + k4)     = h01;
    *(__nv_bfloat162*)(row + hi2 * K + k4 + 2) = h23;
    *(__nv_bfloat162*)(row + lo_slot * K + k4)     = l01;
    *(__nv_bfloat162*)(row + lo_slot * K + k4 + 2) = l23;
}

/* ------------------------------------------------------------------ */
/* HMMA GEMM (validated round 10: 240 TF/s, rel_err 2.5e-5). UNCHANGED */
/* ------------------------------------------------------------------ */
#define G_STRIDE 40

__global__ __launch_bounds__(256, 2) void gemm_mma(
    int M, int Nn,
    const __nv_bfloat16* __restrict__ A,
    const __nv_bfloat16* __restrict__ B,
    float* __restrict__ C)
{
    __shared__ __align__(16) __nv_bfloat16 sA[2][128][G_STRIDE];
    __shared__ __align__(16) __nv_bfloat16 sB[2][128][G_STRIDE];

    const int tid  = threadIdx.x;
    const int lane = tid & 31;
    const int wid  = tid >> 5;
    const int wm   = wid & 1;
    const int wn   = wid >> 1;
    const int bm   = blockIdx.y * 128;
    const int bn   = blockIdx.x * 128;

    const int r0g = tid >> 2, s0g = (tid & 3);
    const int r1g = (tid + 256) >> 2, s1g = s0g;

    const __nv_bfloat16* Ag0 = A + (size_t)(bm + r0g) * GK3 + s0g * 8;
    const __nv_bfloat16* Ag1 = A + (size_t)(bm + r1g) * GK3 + s1g * 8;
    const __nv_bfloat16* Bg0 = B + (size_t)(bn + r0g) * GK3 + s0g * 8;
    const __nv_bfloat16* Bg1 = B + (size_t)(bn + r1g) * GK3 + s1g * 8;

    float acc[4][4][4];
#pragma unroll
    for (int i = 0; i < 4; i++)
#pragma unroll
        for (int j = 0; j < 4; j++)
#pragma unroll
            for (int e = 0; e < 4; e++) acc[i][j][e] = 0.f;

    const uint32_t sAb = smem_u32(&sA[0][0][0]);
    const uint32_t sBb = smem_u32(&sB[0][0][0]);
    const uint32_t BUFB = 128 * G_STRIDE * 2;

    const int aRow = wm * 64 + (lane & 15);
    const int aCol = (lane >> 4) * 8;
    const int bRow = wn * 32 + (lane & 7);
    const int bCol = ((lane >> 3) & 1) * 8;

    {
        uint4 a0 = *(const uint4*)Ag0;
        uint4 a1 = *(const uint4*)Ag1;
        uint4 b0 = *(const uint4*)Bg0;
        uint4 b1 = *(const uint4*)Bg1;
        *(uint4*)&sA[0][r0g][s0g * 8] = a0;
        *(uint4*)&sA[0][r1g][s1g * 8] = a1;
        *(uint4*)&sB[0][r0g][s0g * 8] = b0;
        *(uint4*)&sB[0][r1g][s1g * 8] = b1;
    }
    __syncthreads();

    const int NIT = GK3 / 32;
    int cur = 0;

    for (int c = 0; c < NIT; c++) {
        const bool has_next = (c + 1) < NIT;
        uint4 la0, la1, lb0, lb1;
        if (has_next) {
            const size_t off = (size_t)(c + 1) * 32;
            la0 = *(const uint4*)(Ag0 + off);
            la1 = *(const uint4*)(Ag1 + off);
            lb0 = *(const uint4*)(Bg0 + off);
            lb1 = *(const uint4*)(Bg1 + off);
        }

        const uint32_t aBase = sAb + cur * BUFB;
        const uint32_t bBase = sBb + cur * BUFB;
#pragma unroll
        for (int ks = 0; ks < 2; ks++) {
            uint32_t af[4][4], bf[4][2];
#pragma unroll
            for (int mi = 0; mi < 4; mi++)
                ldsm_x4(af[mi], aBase +
                        (uint32_t)((aRow + mi * 16) * (G_STRIDE * 2)
                                   + (ks * 16 + aCol) * 2));
#pragma unroll
            for (int ni = 0; ni < 4; ni++)
                ldsm_x2(bf[ni], bBase +
                        (uint32_t)((bRow + ni * 8) * (G_STRIDE * 2)
                                   + (ks * 16 + bCol) * 2));
#pragma unroll
            for (int mi = 0; mi < 4; mi++)
#pragma unroll
                for (int ni = 0; ni < 4; ni++)
                    mma_bf16(acc[mi][ni], af[mi], bf[ni]);
        }

        if (has_next) {
            const int nxt = cur ^ 1;
            *(uint4*)&sA[nxt][r0g][s0g * 8] = la0;
            *(uint4*)&sA[nxt][r1g][s1g * 8] = la1;
            *(uint4*)&sB[nxt][r0g][s0g * 8] = lb0;
            *(uint4*)&sB[nxt][r1g][s1g * 8] = lb1;
            __syncthreads();
            cur = nxt;
        }
    }

    const int erow = bm + wm * 64 + (lane >> 2);
    const int ecol = bn + wn * 32 + (lane & 3) * 2;
#pragma unroll
    for (int mi = 0; mi < 4; mi++)
#pragma unroll
        for (int ni = 0; ni < 4; ni++) {
            float* p0 = C + (size_t)(erow + mi * 16) * Nn + ecol + ni * 8;
            float* p1 = p0 + 8 * Nn;
            *(float2*)p0 = make_float2(acc[mi][ni][0], acc[mi][ni][1]);
            *(float2*)p1 = make_float2(acc[mi][ni][2], acc[mi][ni][3]);
        }
}

/* ------------------------------------------------------------------ */
/* Fused RMSNorm + RoPE + transpose (validated; UNCHANGED)             */
/* ------------------------------------------------------------------ */
__global__ __launch_bounds__(128) void norm_rope_kernel(
    const float* __restrict__ qkv,
    const float* __restrict__ q_gamma,
    const float* __restrict__ k_gamma,
    const float* __restrict__ freqs,
    float* __restrict__ Qo, float* __restrict__ Ko, float* __restrict__ Vo)
{
    const int t = blockIdx.x;
    const int h = blockIdx.y;
    const int d = threadIdx.x;
    const int b = t >> 11;
    const int n = t & (NSEQ - 1);

    const float* base = qkv + (size_t)t * (3 * INNER) + h * HD;
    float qv = base[d];
    float kv = base[INNER + d];
    float vv = base[2 * INNER + d];

    __shared__ float red[8];
    float sq = qv * qv, sk = kv * kv;
#pragma unroll
    for (int off = 16; off >= 1; off >>= 1) {
        sq += __shfl_xor_sync(0xffffffffu, sq, off);
        sk += __shfl_xor_sync(0xffffffffu, sk, off);
    }
    const int warp = d >> 5, lane = d & 31;
    if (lane == 0) { red[warp] = sq; red[4 + warp] = sk; }
    __syncthreads();
    float sumq = red[0] + red[1] + red[2] + red[3];
    float sumk = red[4] + red[5] + red[6] + red[7];

    float rq = rsqrtf(sumq * (1.0f / HD) + EPS);
    float rk = rsqrtf(sumk * (1.0f / HD) + EPS);
    float qn = qv * rq * q_gamma[d];
    float kn = kv * rk * k_gamma[d];

    const int p = d >> 1;
    const float* f = freqs + ((size_t)t * (HD / 2) + p) * 2;
    float c = f[0], s = f[1];
    float qp = __shfl_xor_sync(0xffffffffu, qn, 1);
    float kp = __shfl_xor_sync(0xffffffffu, kn, 1);
    float qo, ko;
    if ((d & 1) == 0) { qo = qn * c - qp * s;  ko = kn * c - kp * s; }
    else              { qo = qp * s + qn * c;  ko = kp * s + kn * c; }

    size_t oidx = (((size_t)(b * NH + h)) * NSEQ + n) * HD + d;
    Qo[oidx] = qo; Ko[oidx] = ko; Vo[oidx] = vv;
}

/* ------------------------------------------------------------------ */
/* Flash attention via bf16 mma.sync, 3-term hi/lo splits.             */
/* 4 warps / 128 thr, q-tile 64 (warp owns 16 rows), kv-tile 64.       */
/* smem (bf16, row stride 136 = 272B -> conflict-free ldmatrix):       */
/*   QH | QL (persistent)  KH | KL  (aliased with VH | VL per tile)    */
/* S = Qhi.Khi + Qhi.Klo + Qlo.Khi  (K row-major IS the col-B operand) */
/* O += Phi.Vhi + Phi.Vlo + Plo.Vhi (P repacked reg-only: C-frag ==    */
/* A-frag layout; V B-frags via ldmatrix.x2.trans on row-major V).     */
/* ------------------------------------------------------------------ */
#define AT_STRIDE 136
#define AT_QH 0
#define AT_QL 17408
#define AT_KH 34816
#define AT_KL 52224
#define AT_TOTAL 69632

__global__ __launch_bounds__(128, 2) void attn_mma(
    const float* __restrict__ Q,
    const float* __restrict__ K,
    const float* __restrict__ V,
    float* __restrict__ O)
{
    extern __shared__ char smc[];
    const uint32_t sb = smem_u32(smc);
    const int tid = threadIdx.x, lane = tid & 31, w = tid >> 5;
    const int bh = blockIdx.y, q0 = blockIdx.x * 64;
    const int b = bh >> 4, h = bh & 15;

    const float* Qb = Q + (size_t)bh * NSEQ * HD;
    const float* Kb = K + (size_t)bh * NSEQ * HD;
    const float* Vb = V + (size_t)bh * NSEQ * HD;

    /* load + split Q (pre-scaled by 1/sqrt(HD)) */
    for (int i = tid; i < 64 * 32; i += 128) {
        int r = i >> 5, c4 = i & 31;
        float4 v = *(const float4*)&Qb[(size_t)(q0 + r) * HD + c4 * 4];
        v.x *= QK_SCALE; v.y *= QK_SCALE; v.z *= QK_SCALE; v.w *= QK_SCALE;
        uint32_t h01, l01, h23, l23;
        split2(v.x, v.y, h01, l01);
        split2(v.z, v.w, h23, l23);
        uint32_t off = (uint32_t)(r * AT_STRIDE + c4 * 4) * 2;
        *(uint32_t*)(smc + AT_QH + off)     = h01;
        *(uint32_t*)(smc + AT_QH + off + 4) = h23;
        *(uint32_t*)(smc + AT_QL + off)     = l01;
        *(uint32_t*)(smc + AT_QL + off + 4) = l23;
    }

    float of[16][4];
#pragma unroll
    for (int nd = 0; nd < 16; nd++)
#pragma unroll
        for (int e = 0; e < 4; e++) of[nd][e] = 0.f;
    float m0 = -1e30f, m1 = -1e30f, l0 = 0.f, l1 = 0.f;

    /* fragment address offsets (bytes) */
    const uint32_t aOff  = (uint32_t)((w * 16 + (lane & 15)) * AT_STRIDE
                                      + (lane >> 4) * 8) * 2;
    const uint32_t bKOff = (uint32_t)((lane & 7) * AT_STRIDE
                                      + ((lane >> 3) & 1) * 8) * 2;
    const uint32_t vOff  = (uint32_t)((lane & 15) * AT_STRIDE) * 2;

    for (int kt = 0; kt < NSEQ; kt += 64) {
        __syncthreads();   /* prev PV done reading V; Q visible (iter 0) */

        /* K tile -> KH/KL (row-major [kv][d], no transpose needed) */
        for (int i = tid; i < 64 * 32; i += 128) {
            int r = i >> 5, c4 = i & 31;
            float4 v = *(const float4*)&Kb[(size_t)(kt + r) * HD + c4 * 4];
            uint32_t h01, l01, h23, l23;
            split2(v.x, v.y, h01, l01);
            split2(v.z, v.w, h23, l23);
            uint32_t off = (uint32_t)(r * AT_STRIDE + c4 * 4) * 2;
            *(uint32_t*)(smc + AT_KH + off)     = h01;
            *(uint32_t*)(smc + AT_KH + off + 4) = h23;
            *(uint32_t*)(smc + AT_KL + off)     = l01;
            *(uint32_t*)(smc + AT_KL + off + 4) = l23;
        }
        __syncthreads();

        /* S = Q K^T : warp computes 16x64, 3 split-products over d */
        float s[8][4];
#pragma unroll
        for (int ni = 0; ni < 8; ni++)
#pragma unroll
            for (int e = 0; e < 4; e++) s[ni][e] = 0.f;

#pragma unroll
        for (int seg = 0; seg < 3; seg++) {
            const uint32_t aBase = sb + (seg == 2 ? AT_QL : AT_QH);
            const uint32_t bBase = sb + (seg == 1 ? AT_KL : AT_KH);
#pragma unroll
            for (int ks = 0; ks < 8; ks++) {
                uint32_t af[4];
                ldsm_x4(af, aBase + aOff + ks * 32);
#pragma unroll
                for (int ni = 0; ni < 8; ni++) {
                    uint32_t bf[2];
                    ldsm_x2(bf, bBase + bKOff
                                + (uint32_t)(ni * 8 * AT_STRIDE) * 2 + ks * 32);
                    mma_bf16(s[ni], af, bf);
                }
            }
        }

        /* online softmax: rows g = w*16+lane/4 (elems 0,1) and g+8 (2,3);
           row spread over quad lanes -> shfl_xor 1,2 */
        float tm0 = -1e30f, tm1 = -1e30f;
#pragma unroll
        for (int ni = 0; ni < 8; ni++) {
            tm0 = fmaxf(tm0, fmaxf(s[ni][0], s[ni][1]));
            tm1 = fmaxf(tm1, fmaxf(s[ni][2], s[ni][3]));
        }
        tm0 = fmaxf(tm0, __shfl_xor_sync(0xffffffffu, tm0, 1));
        tm0 = fmaxf(tm0, __shfl_xor_sync(0xffffffffu, tm0, 2));
        tm1 = fmaxf(tm1, __shfl_xor_sync(0xffffffffu, tm1, 1));
        tm1 = fmaxf(tm1, __shfl_xor_sync(0xffffffffu, tm1, 2));
        float mn0 = fmaxf(m0, tm0), mn1 = fmaxf(m1, tm1);
        float c0 = __expf(m0 - mn0), c1 = __expf(m1 - mn1);
        m0 = mn0; m1 = mn1;
        float ls0 = 0.f, ls1 = 0.f;
#pragma unroll
        for (int ni = 0; ni < 8; ni++) {
            s[ni][0] = __expf(s[ni][0] - mn0);
            s[ni][1] = __expf(s[ni][1] - mn0);
            s[ni][2] = __expf(s[ni][2] - mn1);
            s[ni][3] = __expf(s[ni][3] - mn1);
            ls0 += s[ni][0] + s[ni][1];
            ls1 += s[ni][2] + s[ni][3];
        }
        ls0 += __shfl_xor_sync(0xffffffffu, ls0, 1);
        ls0 += __shfl_xor_sync(0xffffffffu, ls0, 2);
        ls1 += __shfl_xor_sync(0xffffffffu, ls1, 1);
        ls1 += __shfl_xor_sync(0xffffffffu, ls1, 2);
        l0 = l0 * c0 + ls0;
        l1 = l1 * c1 + ls1;
#pragma unroll
        for (int nd = 0; nd < 16; nd++) {
            of[nd][0] *= c0; of[nd][1] *= c0;
            of[nd][2] *= c1; of[nd][3] *= c1;
        }

        /* pack P into A-frags (C-frag layout == A-frag layout), hi+lo */
        uint32_t ph[4][4], pl[4][4];
#pragma unroll
        for (int kc = 0; kc < 4; kc++) {
            split2(s[2 * kc][0],     s[2 * kc][1],     ph[kc][0], pl[kc][0]);
            split2(s[2 * kc][2],     s[2 * kc][3],     ph[kc][1], pl[kc][1]);
            split2(s[2 * kc + 1][0], s[2 * kc + 1][1], ph[kc][2], pl[kc][2]);
            split2(s[2 * kc + 1][2], s[2 * kc + 1][3], ph[kc][3], pl[kc][3]);
        }

        __syncthreads();   /* all warps done reading K before V overwrite */

        /* V tile -> VH/VL (aliases KH/KL), row-major [kv][d] */
        for (int i = tid; i < 64 * 32; i += 128) {
            int r = i >> 5, c4 = i & 31;
            float4 v = *(const float4*)&Vb[(size_t)(kt + r) * HD + c4 * 4];
            uint32_t h01, l01, h23, l23;
            split2(v.x, v.y, h01, l01);
            split2(v.z, v.w, h23, l23);
            uint32_t off = (uint32_t)(r * AT_STRIDE + c4 * 4) * 2;
            *(uint32_t*)(smc + AT_KH + off)     = h01;
            *(uint32_t*)(smc + AT_KH + off + 4) = h23;
            *(uint32_t*)(smc + AT_KL + off)     = l01;
            *(uint32_t*)(smc + AT_KL + off + 4) = l23;
        }
        __syncthreads();

        /* O += P V : 3 split-products over kv; B-frags via trans ldsm */
#pragma unroll
        for (int seg = 0; seg < 3; seg++) {
            const uint32_t vBase = sb + (seg == 1 ? AT_KL : AT_KH);
            const uint32_t (*af)[4] = (seg == 2) ? pl : ph;
#pragma unroll
            for (int kc = 0; kc < 4; kc++)
#pragma unroll
                for (int nd = 0; nd < 16; nd++) {
                    uint32_t bv[2];
                    ldsm_x2_t(bv, vBase + vOff +
                              (uint32_t)(kc * 16 * AT_STRIDE + nd * 8) * 2);
                    mma_bf16(of[nd], af[kc], bv);
                }
        }
    }

    /* epilogue: normalize, write [B,N,H*HD] */
    float i0 = 1.f / l0, i1 = 1.f / l1;
    int r0 = q0 + w * 16 + (lane >> 2);
    int cb = h * HD + (lane & 3) * 2;
    float* d0 = O + ((size_t)b * NSEQ + r0) * INNER + cb;
    float* d1 = d0 + 8 * INNER;
#pragma unroll
    for (int nd = 0; nd < 16; nd++) {
        *(float2*)(d0 + nd * 8) = make_float2(of[nd][0] * i0, of[nd][1] * i0);
        *(float2*)(d1 + nd * 8) = make_float2(of[nd][2] * i1, of[nd][3] * i1);
    }
}

/* ------------------------------------------------------------------ */
extern "C" void kernel_launch(void* const* d_in, const int* in_sizes, int n_in,
                              void* d_out, int out_size)
{
    const float *x = nullptr, *Wqkv = nullptr, *qg = nullptr, *kg = nullptr,
                *Wout = nullptr, *freqs = nullptr;
    for (int i = 0; i < n_in; i++) {
        const float* p = (const float*)d_in[i];
        switch (in_sizes[i]) {
            case 8388608:  x     = p; break;   /* [2,2048,2048] */
            case 12582912: Wqkv  = p; break;   /* [6144,2048]   */
            case 4194304:  Wout  = p; break;   /* [2048,2048]   */
            case 524288:   freqs = p; break;   /* [2,2048,64,2] */
            case 128:      if (!qg) qg = p; else kg = p; break;
            default: break;
        }
    }

    float *qkv, *q, *k, *v, *att;
    __nv_bfloat16 *A3, *B3;
    cudaGetSymbolAddress((void**)&qkv, g_qkv);
    cudaGetSymbolAddress((void**)&q,   g_q);
    cudaGetSymbolAddress((void**)&k,   g_k);
    cudaGetSymbolAddress((void**)&v,   g_v);
    cudaGetSymbolAddress((void**)&att, g_att);
    cudaGetSymbolAddress((void**)&A3,  g_A3);
    cudaGetSymbolAddress((void**)&B3,  g_B3);

    cudaFuncSetAttribute(attn_mma,
                         cudaFuncAttributeMaxDynamicSharedMemorySize,
                         AT_TOTAL);

    /* 1. QKV projection via bf16 mma (3-term split, fp32 accum) */
    {
        size_t qa = ((size_t)TTOT * DIMSZ) >> 2;
        size_t qb = ((size_t)(3 * INNER) * DIMSZ) >> 2;
        split3_kernel<<<(int)((qa + 255) / 256), 256>>>(x,    A3, TTOT,      DIMSZ, 2);
        split3_kernel<<<(int)((qb + 255) / 256), 256>>>(Wqkv, B3, 3 * INNER, DIMSZ, 1);
        gemm_mma<<<dim3(3 * INNER / 128, TTOT / 128), 256>>>(
            TTOT, 3 * INNER, A3, B3, qkv);
    }

    /* 2. RMSNorm + RoPE + transpose */
    norm_rope_kernel<<<dim3(TTOT, NH), 128>>>(qkv, qg, kg, freqs, q, k, v);

    /* 3. Attention via bf16 mma (3-term splits) -> [B,N,H*HD] */
    attn_mma<<<dim3(NSEQ / 64, NB * NH), 128, AT_TOTAL>>>(q, k, v, att);

    /* 4. Output projection via bf16 mma */
    {
        size_t qa = ((size_t)TTOT * INNER) >> 2;
        size_t qb = ((size_t)DIMSZ * INNER) >> 2;
        split3_kernel<<<(int)((qa + 255) / 256), 256>>>(att,  A3, TTOT,  INNER, 2);
        split3_kernel<<<(int)((qb + 255) / 256), 256>>>(Wout, B3, DIMSZ, INNER, 1);
        gemm_mma<<<dim3(DIMSZ / 128, TTOT / 128), 256>>>(
            TTOT, DIMSZ, A3, B3, (float*)d_out);
    }
}